// round 2
// baseline (speedup 1.0000x reference)
#include <cuda_runtime.h>
#include <cstdint>

// Problem constants
#define BB 8
#define LL 384
#define CC 512
#define NHH 8
#define DKK 64
#define NLL 4
#define RIN 53
#define RHH 32

// ---------------- device scratch (no allocations allowed) ----------------
__device__ float g_mask[BB * LL];
__device__ int   g_flag;
__device__ float g_h[(size_t)BB * LL * CC];
__device__ float g_q[(size_t)BB * NHH * LL * DKK];
__device__ float g_k[(size_t)BB * NHH * LL * DKK];
__device__ float g_v[(size_t)BB * NHH * LL * DKK];
__device__ float g_refw[(size_t)NLL * BB * NHH * LL * LL];   // raw ref logits, ~151 MB
__device__ float g_sc[(size_t)BB * NHH * LL * LL];           // ~37.7 MB
__device__ float g_ao[(size_t)BB * LL * CC];
__device__ float g_t1[(size_t)BB * LL * CC];

// ---------------- mask dtype detection ----------------
__global__ void k_detect(const unsigned char* __restrict__ p) {
    __shared__ int sHi, sF3;
    if (threadIdx.x == 0) { sHi = 0; sF3 = 0; }
    __syncthreads();
    int hi = 0, f3 = 0;
    for (int i = threadIdx.x; i < BB * LL; i += blockDim.x) {
        unsigned char v = p[i];
        if (v) {
            if ((i & 3) == 3 && v == 0x3F) f3 = 1;
            else if ((i & 3) != 0) hi = 1;
        }
    }
    if (hi) sHi = 1;
    if (f3) sF3 = 1;
    __syncthreads();
    if (threadIdx.x == 0) g_flag = sF3 ? 2 : (sHi ? 1 : 0);
}

__global__ void k_mask(const unsigned char* __restrict__ p) {
    int i = blockIdx.x * 256 + threadIdx.x;
    if (i >= BB * LL) return;
    int flag = g_flag;
    float m;
    if (flag == 2)      m = (((const float*)p)[i] != 0.0f) ? 1.0f : 0.0f;
    else if (flag == 1) m = (p[i] != 0) ? 1.0f : 0.0f;
    else                m = (p[4 * i] != 0) ? 1.0f : 0.0f;
    g_mask[i] = m;
}

__global__ void k_hinit(const float* __restrict__ x) {
    size_t idx = (size_t)blockIdx.x * 256 + threadIdx.x;
    g_h[idx] = x[idx] * g_mask[idx >> 9];
}

// ---------------- pair-MLP, all 4 layers fused; writes RAW masked logits ----------------
// One block per (b,i). smem ~81.6 KB -> 2 CTAs/SM.
#define REF_SMEM_FLOATS (RIN*128 + 128 + 1024 + 32 + LL + RIN*68 + 64*132)

__global__ void __launch_bounds__(256, 2)
k_ref(const float* __restrict__ refCov, const float* __restrict__ Wr1,
      const float* __restrict__ br1, const float* __restrict__ Wr2,
      const float* __restrict__ br2) {
    extern __shared__ float sm[];
    float* sW1   = sm;                    // [53][128]  col = l*32+m
    float* sB1   = sW1 + RIN * 128;       // [128]
    float* sW2   = sB1 + 128;             // [4][32][8]
    float* sB2   = sW2 + 1024;            // [32]
    float* sMask = sB2 + 32;              // [384]
    float* sRC   = sMask + LL;            // [53][68]
    float* sHid  = sRC + RIN * 68;        // [64][132]

    int t = threadIdx.x;
    int bx = blockIdx.x;
    int b = bx / LL, i = bx % LL;

    for (int idx = t; idx < RIN * 128; idx += 256) {
        int k = idx >> 7, hcol = idx & 127;
        int l = hcol >> 5, m = hcol & 31;
        sW1[idx] = Wr1[(size_t)(l * RIN + k) * RHH + m];
    }
    if (t < 128) { int l = t >> 5, m = t & 31; sB1[t] = br1[l * RHH + m]; }
    for (int idx = t; idx < NLL * RHH * NHH; idx += 256) sW2[idx] = Wr2[idx];
    if (t < 32) sB2[t] = br2[t];
    for (int idx = t; idx < LL; idx += 256) sMask[idx] = g_mask[b * LL + idx];
    __syncthreads();

    const float* rcbase = refCov + (size_t)(b * LL + i) * LL * RIN;
    int tx = t & 31, ty = t >> 5;

    // stage-B fixed combo per thread
    int c = t & 31;
    int cl = c >> 3, chh = c & 7;
    float w2c[RHH];
#pragma unroll
    for (int m = 0; m < RHH; m++) w2c[m] = sW2[(cl * RHH + m) * NHH + chh];
    float b2c = sB2[c];
    int jb = (t >> 5) * 8;
    float* dstrow = g_refw + ((((size_t)cl * BB + b) * NHH + chh) * LL + i) * LL;

    for (int j0 = 0; j0 < LL; j0 += 64) {
        for (int idx = t; idx < 64 * RIN; idx += 256) {
            int jl = idx / RIN, k = idx % RIN;
            sRC[k * 68 + jl] = rcbase[(size_t)(j0 + jl) * RIN + k];
        }
        __syncthreads();

        // stage A: hidden[64][128] = relu(RC @ W1 + b1)
        float acc[8][4];
#pragma unroll
        for (int a = 0; a < 8; a++)
#pragma unroll
            for (int q = 0; q < 4; q++) acc[a][q] = 0.0f;

#pragma unroll 4
        for (int k = 0; k < RIN; k++) {
            float4 bv = *(const float4*)&sW1[k * 128 + tx * 4];
            float4 a0 = *(const float4*)&sRC[k * 68 + ty * 8];
            float4 a1 = *(const float4*)&sRC[k * 68 + ty * 8 + 4];
            float aj[8] = {a0.x, a0.y, a0.z, a0.w, a1.x, a1.y, a1.z, a1.w};
#pragma unroll
            for (int a = 0; a < 8; a++) {
                acc[a][0] += aj[a] * bv.x;
                acc[a][1] += aj[a] * bv.y;
                acc[a][2] += aj[a] * bv.z;
                acc[a][3] += aj[a] * bv.w;
            }
        }
        float4 bias = *(const float4*)&sB1[tx * 4];
#pragma unroll
        for (int a = 0; a < 8; a++) {
            float4 h4;
            h4.x = fmaxf(acc[a][0] + bias.x, 0.0f);
            h4.y = fmaxf(acc[a][1] + bias.y, 0.0f);
            h4.z = fmaxf(acc[a][2] + bias.z, 0.0f);
            h4.w = fmaxf(acc[a][3] + bias.w, 0.0f);
            *(float4*)&sHid[(ty * 8 + a) * 132 + tx * 4] = h4;
        }
        __syncthreads();

        // stage B: logits for 32 (layer,head) combos -> raw masked logits to gmem
        float buf[8];
#pragma unroll
        for (int a = 0; a < 8; a++) {
            int jl = jb + a;
            const float* hrow = &sHid[jl * 132 + cl * RHH];
            float o = b2c;
#pragma unroll
            for (int m = 0; m < RHH; m++) o += hrow[m] * w2c[m];
            int j = j0 + jl;
            buf[a] = (sMask[j] != 0.0f) ? o : -1e30f;
        }
        *(float4*)&dstrow[j0 + jb]     = *(float4*)&buf[0];
        *(float4*)&dstrow[j0 + jb + 4] = *(float4*)&buf[4];
        __syncthreads();
    }
}

// ================= improved SIMT GEMM family: 128x64 tile, 8x4 accum ===========

// QKV fused: grid (24, 24): y>>3 selects Q/K/V, (y&7)*64 = n0
__global__ void __launch_bounds__(256) k_gemm_qkv(
        const float* __restrict__ Wq, const float* __restrict__ Wk,
        const float* __restrict__ Wv, const float* __restrict__ bq,
        const float* __restrict__ bk, const float* __restrict__ bv) {
    __shared__ float As[16][132];
    __shared__ float Ws[16][68];
    int sel = blockIdx.y >> 3;
    const float* W    = (sel == 0) ? Wq : (sel == 1) ? Wk : Wv;
    const float* bias = (sel == 0) ? bq : (sel == 1) ? bk : bv;
    float* OUT        = (sel == 0) ? g_q : (sel == 1) ? g_k : g_v;
    int m0 = blockIdx.x * 128, n0 = (blockIdx.y & 7) * 64;
    int t = threadIdx.x;
    int tx = t & 15, ty = t >> 4;
    int la_r = t >> 2, la_c = t & 3;
    int lw_r = t >> 4, lw_c = t & 15;
    float acc[8][4] = {};
    for (int k0 = 0; k0 < CC; k0 += 16) {
        float4 a0 = *(const float4*)&g_h[(size_t)(m0 + la_r) * CC + k0 + la_c * 4];
        float4 a1 = *(const float4*)&g_h[(size_t)(m0 + 64 + la_r) * CC + k0 + la_c * 4];
        As[la_c * 4 + 0][la_r] = a0.x; As[la_c * 4 + 1][la_r] = a0.y;
        As[la_c * 4 + 2][la_r] = a0.z; As[la_c * 4 + 3][la_r] = a0.w;
        As[la_c * 4 + 0][64 + la_r] = a1.x; As[la_c * 4 + 1][64 + la_r] = a1.y;
        As[la_c * 4 + 2][64 + la_r] = a1.z; As[la_c * 4 + 3][64 + la_r] = a1.w;
        *(float4*)&Ws[lw_r][lw_c * 4] =
            *(const float4*)&W[(size_t)(k0 + lw_r) * CC + n0 + lw_c * 4];
        __syncthreads();
#pragma unroll
        for (int k = 0; k < 16; k++) {
            float4 p0 = *(const float4*)&As[k][ty * 8];
            float4 p1 = *(const float4*)&As[k][ty * 8 + 4];
            float4 b4 = *(const float4*)&Ws[k][tx * 4];
            float aa[8] = {p0.x, p0.y, p0.z, p0.w, p1.x, p1.y, p1.z, p1.w};
            float bb[4] = {b4.x, b4.y, b4.z, b4.w};
#pragma unroll
            for (int ii = 0; ii < 8; ii++)
#pragma unroll
                for (int jj = 0; jj < 4; jj++) acc[ii][jj] += aa[ii] * bb[jj];
        }
        __syncthreads();
    }
#pragma unroll
    for (int ii = 0; ii < 8; ii++) {
        int m = m0 + ty * 8 + ii;
        int b = m / LL, i = m % LL;
#pragma unroll
        for (int jj = 0; jj < 4; jj++) {
            int n = n0 + tx * 4 + jj;
            int nh = n >> 6, d = n & 63;
            OUT[((size_t)(b * NHH + nh) * LL + i) * DKK + d] = acc[ii][jj] + bias[n];
        }
    }
}

// O-proj: g_ao @ Wo -> g_t1. grid (24, 8)
__global__ void __launch_bounds__(256) k_gemm_o(const float* __restrict__ W,
                                                const float* __restrict__ bias) {
    __shared__ float As[16][132];
    __shared__ float Ws[16][68];
    int m0 = blockIdx.x * 128, n0 = blockIdx.y * 64;
    int t = threadIdx.x;
    int tx = t & 15, ty = t >> 4;
    int la_r = t >> 2, la_c = t & 3;
    int lw_r = t >> 4, lw_c = t & 15;
    float acc[8][4] = {};
    for (int k0 = 0; k0 < CC; k0 += 16) {
        float4 a0 = *(const float4*)&g_ao[(size_t)(m0 + la_r) * CC + k0 + la_c * 4];
        float4 a1 = *(const float4*)&g_ao[(size_t)(m0 + 64 + la_r) * CC + k0 + la_c * 4];
        As[la_c * 4 + 0][la_r] = a0.x; As[la_c * 4 + 1][la_r] = a0.y;
        As[la_c * 4 + 2][la_r] = a0.z; As[la_c * 4 + 3][la_r] = a0.w;
        As[la_c * 4 + 0][64 + la_r] = a1.x; As[la_c * 4 + 1][64 + la_r] = a1.y;
        As[la_c * 4 + 2][64 + la_r] = a1.z; As[la_c * 4 + 3][64 + la_r] = a1.w;
        *(float4*)&Ws[lw_r][lw_c * 4] =
            *(const float4*)&W[(size_t)(k0 + lw_r) * CC + n0 + lw_c * 4];
        __syncthreads();
#pragma unroll
        for (int k = 0; k < 16; k++) {
            float4 p0 = *(const float4*)&As[k][ty * 8];
            float4 p1 = *(const float4*)&As[k][ty * 8 + 4];
            float4 b4 = *(const float4*)&Ws[k][tx * 4];
            float aa[8] = {p0.x, p0.y, p0.z, p0.w, p1.x, p1.y, p1.z, p1.w};
            float bb[4] = {b4.x, b4.y, b4.z, b4.w};
#pragma unroll
            for (int ii = 0; ii < 8; ii++)
#pragma unroll
                for (int jj = 0; jj < 4; jj++) acc[ii][jj] += aa[ii] * bb[jj];
        }
        __syncthreads();
    }
#pragma unroll
    for (int ii = 0; ii < 8; ii++) {
        int m = m0 + ty * 8 + ii;
#pragma unroll
        for (int jj = 0; jj < 4; jj++) {
            int n = n0 + tx * 4 + jj;
            g_t1[(size_t)m * CC + n] = acc[ii][jj] + bias[n];
        }
    }
}

// scores = QK^T/8 with pair mask. grid (3, 6, 64)
__global__ void __launch_bounds__(256) k_scores() {
    __shared__ float As[16][132];
    __shared__ float Ws[16][68];
    int z = blockIdx.z;
    int b = z >> 3;
    int m0 = blockIdx.x * 128, n0 = blockIdx.y * 64;
    const float* Q = g_q + (size_t)z * LL * DKK;
    const float* K = g_k + (size_t)z * LL * DKK;
    int t = threadIdx.x;
    int tx = t & 15, ty = t >> 4;
    int la_r = t >> 2, la_c = t & 3;
    float acc[8][4] = {};
    for (int k0 = 0; k0 < DKK; k0 += 16) {
        float4 a0 = *(const float4*)&Q[(size_t)(m0 + la_r) * DKK + k0 + la_c * 4];
        float4 a1 = *(const float4*)&Q[(size_t)(m0 + 64 + la_r) * DKK + k0 + la_c * 4];
        As[la_c * 4 + 0][la_r] = a0.x; As[la_c * 4 + 1][la_r] = a0.y;
        As[la_c * 4 + 2][la_r] = a0.z; As[la_c * 4 + 3][la_r] = a0.w;
        As[la_c * 4 + 0][64 + la_r] = a1.x; As[la_c * 4 + 1][64 + la_r] = a1.y;
        As[la_c * 4 + 2][64 + la_r] = a1.z; As[la_c * 4 + 3][64 + la_r] = a1.w;
        float4 u = *(const float4*)&K[(size_t)(n0 + la_r) * DKK + k0 + la_c * 4];
        Ws[la_c * 4 + 0][la_r] = u.x; Ws[la_c * 4 + 1][la_r] = u.y;
        Ws[la_c * 4 + 2][la_r] = u.z; Ws[la_c * 4 + 3][la_r] = u.w;
        __syncthreads();
#pragma unroll
        for (int k = 0; k < 16; k++) {
            float4 p0 = *(const float4*)&As[k][ty * 8];
            float4 p1 = *(const float4*)&As[k][ty * 8 + 4];
            float4 b4 = *(const float4*)&Ws[k][tx * 4];
            float aa[8] = {p0.x, p0.y, p0.z, p0.w, p1.x, p1.y, p1.z, p1.w};
            float bb[4] = {b4.x, b4.y, b4.z, b4.w};
#pragma unroll
            for (int ii = 0; ii < 8; ii++)
#pragma unroll
                for (int jj = 0; jj < 4; jj++) acc[ii][jj] += aa[ii] * bb[jj];
        }
        __syncthreads();
    }
    float mj[4];
#pragma unroll
    for (int q = 0; q < 4; q++) mj[q] = g_mask[b * LL + n0 + tx * 4 + q];
    float* out = g_sc + (size_t)z * LL * LL;
#pragma unroll
    for (int ii = 0; ii < 8; ii++) {
        int i = m0 + ty * 8 + ii;
        float mi = g_mask[b * LL + i];
#pragma unroll
        for (int jj = 0; jj < 4; jj++) {
            float v = (mi != 0.0f && mj[jj] != 0.0f) ? acc[ii][jj] * 0.125f : -1e30f;
            out[(size_t)i * LL + n0 + tx * 4 + jj] = v;
        }
    }
}

// ---------------- dual softmax (scores + ref logits) + combine ----------------
__global__ void k_softcomb(int l) {
    int gw = blockIdx.x * 4 + (threadIdx.x >> 5);
    int lane = threadIdx.x & 31;
    int row_i = gw % LL;
    int z = gw / LL;
    int b = z >> 3;
    float* sc = g_sc + (size_t)z * LL * LL + (size_t)row_i * LL;
    if (g_mask[b * LL + row_i] == 0.0f) {
        for (int j = lane; j < LL; j += 32) sc[j] = 0.0f;
        return;
    }
    const float* rw = g_refw + (((size_t)l * BB * NHH + z) * LL + row_i) * LL;
    float vals[12], rv[12];
    float mx = -3.4e38f, rmx = -3.4e38f;
#pragma unroll
    for (int r = 0; r < 12; r++) {
        vals[r] = sc[lane + r * 32]; mx = fmaxf(mx, vals[r]);
        rv[r] = rw[lane + r * 32];   rmx = fmaxf(rmx, rv[r]);
    }
#pragma unroll
    for (int o = 16; o > 0; o >>= 1) {
        mx  = fmaxf(mx,  __shfl_xor_sync(0xffffffffu, mx, o));
        rmx = fmaxf(rmx, __shfl_xor_sync(0xffffffffu, rmx, o));
    }
    float s = 0.0f, rs = 0.0f;
#pragma unroll
    for (int r = 0; r < 12; r++) {
        vals[r] = expf(vals[r] - mx); s += vals[r];
        rv[r]   = expf(rv[r] - rmx);  rs += rv[r];
    }
#pragma unroll
    for (int o = 16; o > 0; o >>= 1) {
        s  += __shfl_xor_sync(0xffffffffu, s, o);
        rs += __shfl_xor_sync(0xffffffffu, rs, o);
    }
    float inv = 0.5f / s, rinv = 0.5f / rs;
#pragma unroll
    for (int r = 0; r < 12; r++)
        sc[lane + r * 32] = vals[r] * inv + rv[r] * rinv;
}

// ---------------- out = comb @ V -> g_ao. grid (3, 64) ----------------
__global__ void __launch_bounds__(256) k_av() {
    __shared__ float As[16][132];
    __shared__ float Ws[16][68];
    int z = blockIdx.y;
    int b = z >> 3, nh = z & 7;
    const float* Amat = g_sc + (size_t)z * LL * LL;
    const float* V = g_v + (size_t)z * LL * DKK;
    int m0 = blockIdx.x * 128;
    int t = threadIdx.x;
    int tx = t & 15, ty = t >> 4;
    int la_r = t >> 2, la_c = t & 3;
    int lw_r = t >> 4, lw_c = t & 15;
    float acc[8][4] = {};
    for (int k0 = 0; k0 < LL; k0 += 16) {
        float4 a0 = *(const float4*)&Amat[(size_t)(m0 + la_r) * LL + k0 + la_c * 4];
        float4 a1 = *(const float4*)&Amat[(size_t)(m0 + 64 + la_r) * LL + k0 + la_c * 4];
        As[la_c * 4 + 0][la_r] = a0.x; As[la_c * 4 + 1][la_r] = a0.y;
        As[la_c * 4 + 2][la_r] = a0.z; As[la_c * 4 + 3][la_r] = a0.w;
        As[la_c * 4 + 0][64 + la_r] = a1.x; As[la_c * 4 + 1][64 + la_r] = a1.y;
        As[la_c * 4 + 2][64 + la_r] = a1.z; As[la_c * 4 + 3][64 + la_r] = a1.w;
        *(float4*)&Ws[lw_r][lw_c * 4] =
            *(const float4*)&V[(size_t)(k0 + lw_r) * DKK + lw_c * 4];
        __syncthreads();
#pragma unroll
        for (int k = 0; k < 16; k++) {
            float4 p0 = *(const float4*)&As[k][ty * 8];
            float4 p1 = *(const float4*)&As[k][ty * 8 + 4];
            float4 b4 = *(const float4*)&Ws[k][tx * 4];
            float aa[8] = {p0.x, p0.y, p0.z, p0.w, p1.x, p1.y, p1.z, p1.w};
            float bb[4] = {b4.x, b4.y, b4.z, b4.w};
#pragma unroll
            for (int ii = 0; ii < 8; ii++)
#pragma unroll
                for (int jj = 0; jj < 4; jj++) acc[ii][jj] += aa[ii] * bb[jj];
        }
        __syncthreads();
    }
#pragma unroll
    for (int ii = 0; ii < 8; ii++) {
        int i = m0 + ty * 8 + ii;
#pragma unroll
        for (int jj = 0; jj < 4; jj++) {
            int d = tx * 4 + jj;
            g_ao[((size_t)(b * LL + i)) * CC + nh * DKK + d] = acc[ii][jj];
        }
    }
}

// ---------------- residual + layernorm ----------------
template <int FINAL>
__global__ void k_ln(const float* __restrict__ gam, const float* __restrict__ bet) {
    __shared__ float red[8];
    int r = blockIdx.x, t = threadIdx.x;
    const float* a = g_h + (size_t)r * CC;
    const float* bb = g_t1 + (size_t)r * CC;
    float v[4];
    float s = 0.0f;
#pragma unroll
    for (int q = 0; q < 4; q++) {
        int cidx = t + q * 128;
        float x = FINAL ? a[cidx] : (a[cidx] + bb[cidx]);
        v[q] = x;
        s += x;
    }
#pragma unroll
    for (int o = 16; o > 0; o >>= 1) s += __shfl_xor_sync(0xffffffffu, s, o);
    if ((t & 31) == 0) red[t >> 5] = s;
    __syncthreads();
    float mu = (red[0] + red[1] + red[2] + red[3]) * (1.0f / 512.0f);
    float vs = 0.0f;
#pragma unroll
    for (int q = 0; q < 4; q++) { float d = v[q] - mu; vs += d * d; }
#pragma unroll
    for (int o = 16; o > 0; o >>= 1) vs += __shfl_xor_sync(0xffffffffu, vs, o);
    if ((t & 31) == 0) red[4 + (t >> 5)] = vs;
    __syncthreads();
    float var = (red[4] + red[5] + red[6] + red[7]) * (1.0f / 512.0f);
    float rs = rsqrtf(var + 1e-5f);
    float* out = FINAL ? (g_t1 + (size_t)r * CC) : (g_h + (size_t)r * CC);
#pragma unroll
    for (int q = 0; q < 4; q++) {
        int cidx = t + q * 128;
        out[cidx] = (v[q] - mu) * rs * gam[cidx] + bet[cidx];
    }
}

// ---------------- final masked sum over L ----------------
__global__ void k_finred(float* __restrict__ out) {
    int b = blockIdx.x;
    int cidx = blockIdx.y * 128 + threadIdx.x;
    float s = 0.0f;
#pragma unroll 4
    for (int i = 0; i < LL; i++)
        s += g_mask[b * LL + i] * g_t1[((size_t)(b * LL + i)) * CC + cidx];
    out[b * CC + cidx] = s;
}

// ---------------- host launch ----------------
extern "C" void kernel_launch(void* const* d_in, const int* in_sizes, int n_in,
                              void* d_out, int out_size) {
    const float* x            = (const float*)d_in[0];
    const unsigned char* mraw = (const unsigned char*)d_in[1];
    const float* refCov       = (const float*)d_in[2];
    const float* Wq  = (const float*)d_in[3];
    const float* bq  = (const float*)d_in[4];
    const float* Wk  = (const float*)d_in[5];
    const float* bk  = (const float*)d_in[6];
    const float* Wv  = (const float*)d_in[7];
    const float* bv  = (const float*)d_in[8];
    const float* Wo  = (const float*)d_in[9];
    const float* bo  = (const float*)d_in[10];
    const float* Wr1 = (const float*)d_in[11];
    const float* br1 = (const float*)d_in[12];
    const float* Wr2 = (const float*)d_in[13];
    const float* br2 = (const float*)d_in[14];
    const float* ln_g = (const float*)d_in[15];
    const float* ln_b = (const float*)d_in[16];
    const float* fn_g = (const float*)d_in[17];
    const float* fn_b = (const float*)d_in[18];
    (void)in_sizes; (void)n_in; (void)out_size;

    cudaFuncSetAttribute(k_ref, cudaFuncAttributeMaxDynamicSharedMemorySize,
                         REF_SMEM_FLOATS * (int)sizeof(float));

    k_detect<<<1, 256>>>(mraw);
    k_mask<<<(BB * LL + 255) / 256, 256>>>(mraw);
    k_hinit<<<(BB * LL * CC) / 256, 256>>>(x);
    k_ref<<<BB * LL, 256, REF_SMEM_FLOATS * sizeof(float)>>>(refCov, Wr1, br1, Wr2, br2);

    for (int l = 0; l < NLL; l++) {
        const float* wq = Wq + (size_t)l * CC * CC;
        const float* wk = Wk + (size_t)l * CC * CC;
        const float* wv = Wv + (size_t)l * CC * CC;
        const float* wo = Wo + (size_t)l * CC * CC;
        k_gemm_qkv<<<dim3(24, 24), 256>>>(wq, wk, wv, bq + l * CC, bk + l * CC, bv + l * CC);
        k_scores<<<dim3(3, 6, BB * NHH), 256>>>();
        k_softcomb<<<(BB * NHH * LL) / 4, 128>>>(l);
        k_av<<<dim3(3, BB * NHH), 256>>>();
        k_gemm_o<<<dim3(24, 8), 256>>>(wo, bo + l * CC);
        k_ln<0><<<BB * LL, 128>>>(ln_g + l * CC, ln_b + l * CC);
    }
    k_ln<1><<<BB * LL, 128>>>(fn_g, fn_b);
    k_finred<<<dim3(BB, CC / 128), 128>>>((float*)d_out);
}

// round 4
// speedup vs baseline: 1.5990x; 1.5990x over previous
#include <cuda_runtime.h>
#include <cstdint>

#define BB 8
#define LL 384
#define CC 512
#define NHH 8
#define DKK 64
#define NLL 4
#define RIN 53
#define RHH 32

__device__ float g_mask[BB * LL];
__device__ int   g_flag;
__device__ float g_h[(size_t)BB * LL * CC];
__device__ float g_q[(size_t)BB * NHH * LL * DKK];
__device__ float g_k[(size_t)BB * NHH * LL * DKK];
__device__ float g_v[(size_t)BB * NHH * LL * DKK];
__device__ float g_refw[(size_t)NLL * BB * NHH * LL * LL];
__device__ float g_sc[(size_t)BB * NHH * LL * LL];
__device__ float g_ao[(size_t)BB * LL * CC];
__device__ float g_t1[(size_t)BB * LL * CC];

// ---------- tf32 helpers ----------
__device__ __forceinline__ float to_tf32(float x) {
    uint32_t r; asm("cvt.rna.tf32.f32 %0, %1;" : "=r"(r) : "f"(x));
    return __uint_as_float(r);
}
__device__ __forceinline__ void split_tf32(float x, float& hi, float& lo) {
    hi = to_tf32(x); lo = to_tf32(x - hi);
}
__device__ __forceinline__ void mma_tf32(float* c, const uint32_t* a, uint32_t b0, uint32_t b1) {
    asm("mma.sync.aligned.m16n8k8.row.col.f32.tf32.tf32.f32 "
        "{%0,%1,%2,%3},{%4,%5,%6,%7},{%8,%9},{%0,%1,%2,%3};"
        : "+f"(c[0]), "+f"(c[1]), "+f"(c[2]), "+f"(c[3])
        : "r"(a[0]), "r"(a[1]), "r"(a[2]), "r"(a[3]), "r"(b0), "r"(b1));
}

// ---------- mask detection ----------
__global__ void k_detect(const unsigned char* __restrict__ p) {
    __shared__ int sHi, sF3;
    if (threadIdx.x == 0) { sHi = 0; sF3 = 0; }
    __syncthreads();
    int hi = 0, f3 = 0;
    for (int i = threadIdx.x; i < BB * LL; i += blockDim.x) {
        unsigned char v = p[i];
        if (v) {
            if ((i & 3) == 3 && v == 0x3F) f3 = 1;
            else if ((i & 3) != 0) hi = 1;
        }
    }
    if (hi) sHi = 1;
    if (f3) sF3 = 1;
    __syncthreads();
    if (threadIdx.x == 0) g_flag = sF3 ? 2 : (sHi ? 1 : 0);
}

__global__ void k_mask(const unsigned char* __restrict__ p) {
    int i = blockIdx.x * 256 + threadIdx.x;
    if (i >= BB * LL) return;
    int flag = g_flag;
    float m;
    if (flag == 2)      m = (((const float*)p)[i] != 0.0f) ? 1.0f : 0.0f;
    else if (flag == 1) m = (p[i] != 0) ? 1.0f : 0.0f;
    else                m = (p[4 * i] != 0) ? 1.0f : 0.0f;
    g_mask[i] = m;
}

__global__ void k_hinit(const float* __restrict__ x) {
    size_t idx = (size_t)blockIdx.x * 256 + threadIdx.x;
    g_h[idx] = x[idx] * g_mask[idx >> 9];
}

// ---------- pair-MLP (4 layers fused) -> raw masked logits ----------
#define REF_SMEM_FLOATS (RIN*128 + 128 + 1024 + 32 + LL + RIN*68 + 64*132)

__global__ void __launch_bounds__(256, 2)
k_ref(const float* __restrict__ refCov, const float* __restrict__ Wr1,
      const float* __restrict__ br1, const float* __restrict__ Wr2,
      const float* __restrict__ br2) {
    extern __shared__ float sm[];
    float* sW1   = sm;
    float* sB1   = sW1 + RIN * 128;
    float* sW2   = sB1 + 128;
    float* sB2   = sW2 + 1024;
    float* sMask = sB2 + 32;
    float* sRC   = sMask + LL;
    float* sHid  = sRC + RIN * 68;

    int t = threadIdx.x;
    int bx = blockIdx.x;
    int b = bx / LL, i = bx % LL;

    for (int idx = t; idx < RIN * 128; idx += 256) {
        int k = idx >> 7, hcol = idx & 127;
        int l = hcol >> 5, m = hcol & 31;
        sW1[idx] = Wr1[(size_t)(l * RIN + k) * RHH + m];
    }
    if (t < 128) { int l = t >> 5, m = t & 31; sB1[t] = br1[l * RHH + m]; }
    for (int idx = t; idx < NLL * RHH * NHH; idx += 256) sW2[idx] = Wr2[idx];
    if (t < 32) sB2[t] = br2[t];
    for (int idx = t; idx < LL; idx += 256) sMask[idx] = g_mask[b * LL + idx];
    __syncthreads();

    const float* rcbase = refCov + (size_t)(b * LL + i) * LL * RIN;
    int tx = t & 31, ty = t >> 5;

    int c = t & 31;
    int cl = c >> 3, chh = c & 7;
    float w2c[RHH];
#pragma unroll
    for (int m = 0; m < RHH; m++) w2c[m] = sW2[(cl * RHH + m) * NHH + chh];
    float b2c = sB2[c];
    int jb = (t >> 5) * 8;
    float* dstrow = g_refw + ((((size_t)cl * BB + b) * NHH + chh) * LL + i) * LL;

    for (int j0 = 0; j0 < LL; j0 += 64) {
        for (int idx = t; idx < 64 * RIN; idx += 256) {
            int jl = idx / RIN, k = idx % RIN;
            sRC[k * 68 + jl] = rcbase[(size_t)(j0 + jl) * RIN + k];
        }
        __syncthreads();

        float acc[8][4];
#pragma unroll
        for (int a = 0; a < 8; a++)
#pragma unroll
            for (int q = 0; q < 4; q++) acc[a][q] = 0.0f;

#pragma unroll 4
        for (int k = 0; k < RIN; k++) {
            float4 bv = *(const float4*)&sW1[k * 128 + tx * 4];
            float4 a0 = *(const float4*)&sRC[k * 68 + ty * 8];
            float4 a1 = *(const float4*)&sRC[k * 68 + ty * 8 + 4];
            float aj[8] = {a0.x, a0.y, a0.z, a0.w, a1.x, a1.y, a1.z, a1.w};
#pragma unroll
            for (int a = 0; a < 8; a++) {
                acc[a][0] += aj[a] * bv.x;
                acc[a][1] += aj[a] * bv.y;
                acc[a][2] += aj[a] * bv.z;
                acc[a][3] += aj[a] * bv.w;
            }
        }
        float4 bias = *(const float4*)&sB1[tx * 4];
#pragma unroll
        for (int a = 0; a < 8; a++) {
            float4 h4;
            h4.x = fmaxf(acc[a][0] + bias.x, 0.0f);
            h4.y = fmaxf(acc[a][1] + bias.y, 0.0f);
            h4.z = fmaxf(acc[a][2] + bias.z, 0.0f);
            h4.w = fmaxf(acc[a][3] + bias.w, 0.0f);
            *(float4*)&sHid[(ty * 8 + a) * 132 + tx * 4] = h4;
        }
        __syncthreads();

        // stage B: float4 reads (quarter-wavefront broadcast, conflict-free)
        float buf[8];
#pragma unroll
        for (int a = 0; a < 8; a++) {
            int jl = jb + a;
            const float* hrow = &sHid[jl * 132 + cl * RHH];
            float o = b2c;
#pragma unroll
            for (int m4 = 0; m4 < 8; m4++) {
                float4 h4 = *(const float4*)&hrow[m4 * 4];
                o += h4.x * w2c[m4 * 4] + h4.y * w2c[m4 * 4 + 1]
                   + h4.z * w2c[m4 * 4 + 2] + h4.w * w2c[m4 * 4 + 3];
            }
            int j = j0 + jl;
            buf[a] = (sMask[j] != 0.0f) ? o : -1e30f;
        }
        *(float4*)&dstrow[j0 + jb]     = *(float4*)&buf[0];
        *(float4*)&dstrow[j0 + jb + 4] = *(float4*)&buf[4];
        __syncthreads();
    }
}

// ---------- 3xTF32 mma GEMM: C[3072,512] = A @ W + bias ----------
// MODE 0: A=g_ao -> g_t1, grid (48,8).  MODE 1: A=g_h -> q/k/v, grid (48,24).
template <int MODE>
__global__ void __launch_bounds__(256) k_mm(
        const float* __restrict__ W0, const float* __restrict__ W1,
        const float* __restrict__ W2, const float* __restrict__ b0,
        const float* __restrict__ b1, const float* __restrict__ b2) {
    __shared__ float Ah[64 * 20], Al[64 * 20], Bh[16 * 72], Bl[16 * 72];
    int sel = (MODE == 1) ? (blockIdx.y >> 3) : 0;
    const float* A    = (MODE == 0) ? g_ao : g_h;
    const float* W    = (sel == 0) ? W0 : (sel == 1) ? W1 : W2;
    const float* bias = (sel == 0) ? b0 : (sel == 1) ? b1 : b2;
    int m0 = blockIdx.x * 64;
    int n0 = ((MODE == 1) ? (blockIdx.y & 7) : blockIdx.y) * 64;
    int t = threadIdx.x, lane = t & 31, wid = t >> 5;
    int g = lane >> 2, tg = lane & 3;
    int wm = wid & 1, wn = wid >> 1;      // warp tile 32m x 16n
    int ar = t >> 2, ac = t & 3;
    int wr = t >> 4, wc = t & 15;

    float acc[2][2][4] = {};

    for (int k0 = 0; k0 < CC; k0 += 16) {
        float4 a4 = *(const float4*)&A[(size_t)(m0 + ar) * CC + k0 + ac * 4];
        float4 h4, l4;
        split_tf32(a4.x, h4.x, l4.x); split_tf32(a4.y, h4.y, l4.y);
        split_tf32(a4.z, h4.z, l4.z); split_tf32(a4.w, h4.w, l4.w);
        *(float4*)&Ah[ar * 20 + ac * 4] = h4;
        *(float4*)&Al[ar * 20 + ac * 4] = l4;
        float4 w4 = *(const float4*)&W[(size_t)(k0 + wr) * CC + n0 + wc * 4];
        split_tf32(w4.x, h4.x, l4.x); split_tf32(w4.y, h4.y, l4.y);
        split_tf32(w4.z, h4.z, l4.z); split_tf32(w4.w, h4.w, l4.w);
        *(float4*)&Bh[wr * 72 + wc * 4] = h4;
        *(float4*)&Bl[wr * 72 + wc * 4] = l4;
        __syncthreads();

#pragma unroll
        for (int kk = 0; kk < 16; kk += 8) {
            uint32_t ah[2][4], al[2][4];
#pragma unroll
            for (int mt = 0; mt < 2; mt++) {
                int mb = wm * 32 + mt * 16;
                ah[mt][0] = __float_as_uint(Ah[(mb + g) * 20 + kk + tg]);
                ah[mt][1] = __float_as_uint(Ah[(mb + g + 8) * 20 + kk + tg]);
                ah[mt][2] = __float_as_uint(Ah[(mb + g) * 20 + kk + tg + 4]);
                ah[mt][3] = __float_as_uint(Ah[(mb + g + 8) * 20 + kk + tg + 4]);
                al[mt][0] = __float_as_uint(Al[(mb + g) * 20 + kk + tg]);
                al[mt][1] = __float_as_uint(Al[(mb + g + 8) * 20 + kk + tg]);
                al[mt][2] = __float_as_uint(Al[(mb + g) * 20 + kk + tg + 4]);
                al[mt][3] = __float_as_uint(Al[(mb + g + 8) * 20 + kk + tg + 4]);
            }
#pragma unroll
            for (int nt = 0; nt < 2; nt++) {
                int nb = wn * 16 + nt * 8;
                uint32_t bh0 = __float_as_uint(Bh[(kk + tg) * 72 + nb + g]);
                uint32_t bh1 = __float_as_uint(Bh[(kk + tg + 4) * 72 + nb + g]);
                uint32_t bl0 = __float_as_uint(Bl[(kk + tg) * 72 + nb + g]);
                uint32_t bl1 = __float_as_uint(Bl[(kk + tg + 4) * 72 + nb + g]);
#pragma unroll
                for (int mt = 0; mt < 2; mt++) {
                    mma_tf32(acc[mt][nt], ah[mt], bh0, bh1);
                    mma_tf32(acc[mt][nt], al[mt], bh0, bh1);
                    mma_tf32(acc[mt][nt], ah[mt], bl0, bl1);
                }
            }
        }
        __syncthreads();
    }

#pragma unroll
    for (int mt = 0; mt < 2; mt++) {
#pragma unroll
        for (int nt = 0; nt < 2; nt++) {
#pragma unroll
            for (int rh = 0; rh < 2; rh++) {
                int m = m0 + wm * 32 + mt * 16 + g + rh * 8;
                int n = n0 + wn * 16 + nt * 8 + 2 * tg;
                float v0 = acc[mt][nt][rh * 2]     + bias[n];
                float v1 = acc[mt][nt][rh * 2 + 1] + bias[n + 1];
                if (MODE == 0) {
                    *(float2*)&g_t1[(size_t)m * CC + n] = make_float2(v0, v1);
                } else {
                    int bi = m / LL, ii = m % LL, nh = n >> 6, d = n & 63;
                    float* OUT = (sel == 0) ? g_q : (sel == 1) ? g_k : g_v;
                    *(float2*)&OUT[((size_t)(bi * NHH + nh) * LL + ii) * DKK + d] =
                        make_float2(v0, v1);
                }
            }
        }
    }
}

// ---------- scores = QK^T/8 + pair mask (R1 64x64 tiles) ----------
__global__ void __launch_bounds__(256) k_scores() {
    __shared__ float Qs[64][68];
    __shared__ float Ks[64][68];
    int z = blockIdx.z;
    int b = z >> 3;
    int i0 = blockIdx.x * 64, j0 = blockIdx.y * 64;
    const float* Q = g_q + (size_t)z * LL * DKK;
    const float* K = g_k + (size_t)z * LL * DKK;
    int t = threadIdx.x;
#pragma unroll
    for (int rep = 0; rep < 4; rep++) {
        int idx = rep * 256 + t;
        int row = idx >> 4, q = idx & 15;
        float4 v = *(const float4*)&Q[(size_t)(i0 + row) * DKK + q * 4];
        Qs[q * 4 + 0][row] = v.x; Qs[q * 4 + 1][row] = v.y;
        Qs[q * 4 + 2][row] = v.z; Qs[q * 4 + 3][row] = v.w;
        float4 u = *(const float4*)&K[(size_t)(j0 + row) * DKK + q * 4];
        Ks[q * 4 + 0][row] = u.x; Ks[q * 4 + 1][row] = u.y;
        Ks[q * 4 + 2][row] = u.z; Ks[q * 4 + 3][row] = u.w;
    }
    __syncthreads();
    int tx = t & 15, ty = t >> 4;
    float acc[4][4] = {};
#pragma unroll 8
    for (int k = 0; k < 64; k++) {
        float4 a4 = *(const float4*)&Qs[k][ty * 4];
        float4 b4 = *(const float4*)&Ks[k][tx * 4];
        float aa[4] = {a4.x, a4.y, a4.z, a4.w};
        float bb[4] = {b4.x, b4.y, b4.z, b4.w};
#pragma unroll
        for (int ii = 0; ii < 4; ii++)
#pragma unroll
            for (int jj = 0; jj < 4; jj++) acc[ii][jj] += aa[ii] * bb[jj];
    }
    float mi[4], mj[4];
#pragma unroll
    for (int q = 0; q < 4; q++) {
        mi[q] = g_mask[b * LL + i0 + ty * 4 + q];
        mj[q] = g_mask[b * LL + j0 + tx * 4 + q];
    }
    float* out = g_sc + (size_t)z * LL * LL;
#pragma unroll
    for (int ii = 0; ii < 4; ii++)
#pragma unroll
        for (int jj = 0; jj < 4; jj++) {
            float v = (mi[ii] != 0.0f && mj[jj] != 0.0f) ? acc[ii][jj] * 0.125f : -1e30f;
            out[(size_t)(i0 + ty * 4 + ii) * LL + j0 + tx * 4 + jj] = v;
        }
}

// ---------- dual softmax + combine ----------
__global__ void k_softcomb(int l) {
    int gw = blockIdx.x * 4 + (threadIdx.x >> 5);
    int lane = threadIdx.x & 31;
    int row_i = gw % LL;
    int z = gw / LL;
    int b = z >> 3;
    float* sc = g_sc + (size_t)z * LL * LL + (size_t)row_i * LL;
    if (g_mask[b * LL + row_i] == 0.0f) {
        for (int j = lane; j < LL; j += 32) sc[j] = 0.0f;
        return;
    }
    const float* rw = g_refw + (((size_t)l * BB * NHH + z) * LL + row_i) * LL;
    float vals[12], rv[12];
    float mx = -3.4e38f, rmx = -3.4e38f;
#pragma unroll
    for (int r = 0; r < 12; r++) {
        vals[r] = sc[lane + r * 32]; mx = fmaxf(mx, vals[r]);
        rv[r] = rw[lane + r * 32];   rmx = fmaxf(rmx, rv[r]);
    }
#pragma unroll
    for (int o = 16; o > 0; o >>= 1) {
        mx  = fmaxf(mx,  __shfl_xor_sync(0xffffffffu, mx, o));
        rmx = fmaxf(rmx, __shfl_xor_sync(0xffffffffu, rmx, o));
    }
    float s = 0.0f, rs = 0.0f;
#pragma unroll
    for (int r = 0; r < 12; r++) {
        vals[r] = __expf(vals[r] - mx); s += vals[r];
        rv[r]   = __expf(rv[r] - rmx);  rs += rv[r];
    }
#pragma unroll
    for (int o = 16; o > 0; o >>= 1) {
        s  += __shfl_xor_sync(0xffffffffu, s, o);
        rs += __shfl_xor_sync(0xffffffffu, rs, o);
    }
    float inv = 0.5f / s, rinv = 0.5f / rs;
#pragma unroll
    for (int r = 0; r < 12; r++)
        sc[lane + r * 32] = vals[r] * inv + rv[r] * rinv;
}

// ---------- out = comb @ V (R1 64x64 tiles) ----------
__global__ void __launch_bounds__(256) k_av() {
    __shared__ float As[16][68];
    __shared__ float Bs[16][68];
    int z = blockIdx.y;
    int b = z >> 3, nh = z & 7;
    const float* Amat = g_sc + (size_t)z * LL * LL;
    const float* V = g_v + (size_t)z * LL * DKK;
    int m0 = blockIdx.x * 64;
    int t = threadIdx.x;
    int tx = t & 15, ty = t >> 4;
    int la_r = t >> 2, la_c = t & 3;
    int lw_r = t >> 4, lw_c = t & 15;
    float acc[4][4] = {};
    for (int k0 = 0; k0 < LL; k0 += 16) {
        float4 av = *(const float4*)&Amat[(size_t)(m0 + la_r) * LL + k0 + la_c * 4];
        As[la_c * 4 + 0][la_r] = av.x;
        As[la_c * 4 + 1][la_r] = av.y;
        As[la_c * 4 + 2][la_r] = av.z;
        As[la_c * 4 + 3][la_r] = av.w;
        *(float4*)&Bs[lw_r][lw_c * 4] =
            *(const float4*)&V[(size_t)(k0 + lw_r) * DKK + lw_c * 4];
        __syncthreads();
#pragma unroll
        for (int k = 0; k < 16; k++) {
            float4 a4 = *(const float4*)&As[k][ty * 4];
            float4 b4 = *(const float4*)&Bs[k][tx * 4];
            float aa[4] = {a4.x, a4.y, a4.z, a4.w};
            float bb[4] = {b4.x, b4.y, b4.z, b4.w};
#pragma unroll
            for (int ii = 0; ii < 4; ii++)
#pragma unroll
                for (int jj = 0; jj < 4; jj++) acc[ii][jj] += aa[ii] * bb[jj];
        }
        __syncthreads();
    }
#pragma unroll
    for (int ii = 0; ii < 4; ii++) {
        int i = m0 + ty * 4 + ii;
#pragma unroll
        for (int jj = 0; jj < 4; jj++) {
            int d = tx * 4 + jj;
            g_ao[((size_t)(b * LL + i)) * CC + nh * DKK + d] = acc[ii][jj];
        }
    }
}

// ---------- residual + layernorm ----------
template <int FINAL>
__global__ void k_ln(const float* __restrict__ gam, const float* __restrict__ bet) {
    __shared__ float red[8];
    int r = blockIdx.x, t = threadIdx.x;
    const float* a = g_h + (size_t)r * CC;
    const float* bb = g_t1 + (size_t)r * CC;
    float v[4];
    float s = 0.0f;
#pragma unroll
    for (int q = 0; q < 4; q++) {
        int cidx = t + q * 128;
        float x = FINAL ? a[cidx] : (a[cidx] + bb[cidx]);
        v[q] = x;
        s += x;
    }
#pragma unroll
    for (int o = 16; o > 0; o >>= 1) s += __shfl_xor_sync(0xffffffffu, s, o);
    if ((t & 31) == 0) red[t >> 5] = s;
    __syncthreads();
    float mu = (red[0] + red[1] + red[2] + red[3]) * (1.0f / 512.0f);
    float vs = 0.0f;
#pragma unroll
    for (int q = 0; q < 4; q++) { float d = v[q] - mu; vs += d * d; }
#pragma unroll
    for (int o = 16; o > 0; o >>= 1) vs += __shfl_xor_sync(0xffffffffu, vs, o);
    if ((t & 31) == 0) red[4 + (t >> 5)] = vs;
    __syncthreads();
    float var = (red[4] + red[5] + red[6] + red[7]) * (1.0f / 512.0f);
    float rsr = rsqrtf(var + 1e-5f);
    float* out = FINAL ? (g_t1 + (size_t)r * CC) : (g_h + (size_t)r * CC);
#pragma unroll
    for (int q = 0; q < 4; q++) {
        int cidx = t + q * 128;
        out[cidx] = (v[q] - mu) * rsr * gam[cidx] + bet[cidx];
    }
}

// ---------- final masked sum ----------
__global__ void k_finred(float* __restrict__ out) {
    int b = blockIdx.x;
    int cidx = blockIdx.y * 128 + threadIdx.x;
    float s = 0.0f;
#pragma unroll 4
    for (int i = 0; i < LL; i++)
        s += g_mask[b * LL + i] * g_t1[((size_t)(b * LL + i)) * CC + cidx];
    out[b * CC + cidx] = s;
}

// ---------- host launch ----------
extern "C" void kernel_launch(void* const* d_in, const int* in_sizes, int n_in,
                              void* d_out, int out_size) {
    const float* x            = (const float*)d_in[0];
    const unsigned char* mraw = (const unsigned char*)d_in[1];
    const float* refCov       = (const float*)d_in[2];
    const float* Wq  = (const float*)d_in[3];
    const float* bq  = (const float*)d_in[4];
    const float* Wk  = (const float*)d_in[5];
    const float* bk  = (const float*)d_in[6];
    const float* Wv  = (const float*)d_in[7];
    const float* bv  = (const float*)d_in[8];
    const float* Wo  = (const float*)d_in[9];
    const float* bo  = (const float*)d_in[10];
    const float* Wr1 = (const float*)d_in[11];
    const float* br1 = (const float*)d_in[12];
    const float* Wr2 = (const float*)d_in[13];
    const float* br2 = (const float*)d_in[14];
    const float* ln_g = (const float*)d_in[15];
    const float* ln_b = (const float*)d_in[16];
    const float* fn_g = (const float*)d_in[17];
    const float* fn_b = (const float*)d_in[18];
    (void)in_sizes; (void)n_in; (void)out_size;

    cudaFuncSetAttribute(k_ref, cudaFuncAttributeMaxDynamicSharedMemorySize,
                         REF_SMEM_FLOATS * (int)sizeof(float));

    k_detect<<<1, 256>>>(mraw);
    k_mask<<<(BB * LL + 255) / 256, 256>>>(mraw);
    k_hinit<<<(BB * LL * CC) / 256, 256>>>(x);
    k_ref<<<BB * LL, 256, REF_SMEM_FLOATS * sizeof(float)>>>(refCov, Wr1, br1, Wr2, br2);

    for (int l = 0; l < NLL; l++) {
        const float* wq = Wq + (size_t)l * CC * CC;
        const float* wk = Wk + (size_t)l * CC * CC;
        const float* wv = Wv + (size_t)l * CC * CC;
        const float* wo = Wo + (size_t)l * CC * CC;
        k_mm<1><<<dim3(48, 24), 256>>>(wq, wk, wv, bq + l * CC, bk + l * CC, bv + l * CC);
        k_scores<<<dim3(6, 6, BB * NHH), 256>>>();
        k_softcomb<<<(BB * NHH * LL) / 4, 128>>>(l);
        k_av<<<dim3(6, BB * NHH), 256>>>();
        k_mm<0><<<dim3(48, 8), 256>>>(wo, bo + l * CC, nullptr, bo + l * CC, nullptr, nullptr);
        k_ln<0><<<BB * LL, 128>>>(ln_g + l * CC, ln_b + l * CC);
    }
    k_ln<1><<<BB * LL, 128>>>(fn_g, fn_b);
    k_finred<<<dim3(BB, CC / 128), 128>>>((float*)d_out);
}

// round 5
// speedup vs baseline: 1.8112x; 1.1327x over previous
#include <cuda_runtime.h>
#include <cstdint>

#define BB 8
#define LL 384
#define CC 512
#define NHH 8
#define DKK 64
#define NLL 4
#define RIN 53
#define RHH 32

__device__ float g_mask[BB * LL];
__device__ int   g_flag;
__device__ float g_h[(size_t)BB * LL * CC];
__device__ float g_q[(size_t)BB * NHH * LL * DKK];
__device__ float g_k[(size_t)BB * NHH * LL * DKK];
__device__ float g_v[(size_t)BB * NHH * LL * DKK];
__device__ float g_refw[(size_t)NLL * BB * NHH * LL * LL];
__device__ float g_sc[(size_t)BB * NHH * LL * LL];
__device__ float g_ao[(size_t)BB * LL * CC];
__device__ float g_t1[(size_t)BB * LL * CC];

// ---------- tf32 helpers ----------
__device__ __forceinline__ float to_tf32(float x) {
    uint32_t r; asm("cvt.rna.tf32.f32 %0, %1;" : "=r"(r) : "f"(x));
    return __uint_as_float(r);
}
__device__ __forceinline__ void split_tf32(float x, float& hi, float& lo) {
    hi = to_tf32(x); lo = to_tf32(x - hi);
}
__device__ __forceinline__ void split4(float4 a, float4& h, float4& l) {
    split_tf32(a.x, h.x, l.x); split_tf32(a.y, h.y, l.y);
    split_tf32(a.z, h.z, l.z); split_tf32(a.w, h.w, l.w);
}
__device__ __forceinline__ void mma_tf32(float* c, const uint32_t* a, uint32_t b0, uint32_t b1) {
    asm("mma.sync.aligned.m16n8k8.row.col.f32.tf32.tf32.f32 "
        "{%0,%1,%2,%3},{%4,%5,%6,%7},{%8,%9},{%0,%1,%2,%3};"
        : "+f"(c[0]), "+f"(c[1]), "+f"(c[2]), "+f"(c[3])
        : "r"(a[0]), "r"(a[1]), "r"(a[2]), "r"(a[3]), "r"(b0), "r"(b1));
}

// ---------- mask detection ----------
__global__ void k_detect(const unsigned char* __restrict__ p) {
    __shared__ int sHi, sF3;
    if (threadIdx.x == 0) { sHi = 0; sF3 = 0; }
    __syncthreads();
    int hi = 0, f3 = 0;
    for (int i = threadIdx.x; i < BB * LL; i += blockDim.x) {
        unsigned char v = p[i];
        if (v) {
            if ((i & 3) == 3 && v == 0x3F) f3 = 1;
            else if ((i & 3) != 0) hi = 1;
        }
    }
    if (hi) sHi = 1;
    if (f3) sF3 = 1;
    __syncthreads();
    if (threadIdx.x == 0) g_flag = sF3 ? 2 : (sHi ? 1 : 0);
}

__global__ void k_mask(const unsigned char* __restrict__ p) {
    int i = blockIdx.x * 256 + threadIdx.x;
    if (i >= BB * LL) return;
    int flag = g_flag;
    float m;
    if (flag == 2)      m = (((const float*)p)[i] != 0.0f) ? 1.0f : 0.0f;
    else if (flag == 1) m = (p[i] != 0) ? 1.0f : 0.0f;
    else                m = (p[4 * i] != 0) ? 1.0f : 0.0f;
    g_mask[i] = m;
}

__global__ void k_hinit(const float* __restrict__ x) {
    size_t idx = (size_t)blockIdx.x * 256 + threadIdx.x;
    g_h[idx] = x[idx] * g_mask[idx >> 9];
}

// ---------- pair-MLP (4 layers fused) -> raw masked logits ----------
#define REF_SMEM_FLOATS (RIN*128 + 128 + 1024 + 32 + LL + RIN*68 + 64*132)

__global__ void __launch_bounds__(256, 2)
k_ref(const float* __restrict__ refCov, const float* __restrict__ Wr1,
      const float* __restrict__ br1, const float* __restrict__ Wr2,
      const float* __restrict__ br2) {
    extern __shared__ float sm[];
    float* sW1   = sm;
    float* sB1   = sW1 + RIN * 128;
    float* sW2   = sB1 + 128;
    float* sB2   = sW2 + 1024;
    float* sMask = sB2 + 32;
    float* sRC   = sMask + LL;
    float* sHid  = sRC + RIN * 68;

    int t = threadIdx.x;
    int bx = blockIdx.x;
    int b = bx / LL, i = bx % LL;

    for (int idx = t; idx < RIN * 128; idx += 256) {
        int k = idx >> 7, hcol = idx & 127;
        int l = hcol >> 5, m = hcol & 31;
        sW1[idx] = Wr1[(size_t)(l * RIN + k) * RHH + m];
    }
    if (t < 128) { int l = t >> 5, m = t & 31; sB1[t] = br1[l * RHH + m]; }
    for (int idx = t; idx < NLL * RHH * NHH; idx += 256) sW2[idx] = Wr2[idx];
    if (t < 32) sB2[t] = br2[t];
    for (int idx = t; idx < LL; idx += 256) sMask[idx] = g_mask[b * LL + idx];
    __syncthreads();

    const float* rcbase = refCov + (size_t)(b * LL + i) * LL * RIN;
    int tx = t & 31, ty = t >> 5;

    int c = t & 31;
    int cl = c >> 3, chh = c & 7;
    // W2 pre-rotated so stage-B smem reads rotate bank groups per cl
    float w2c[RHH];
#pragma unroll
    for (int m4i = 0; m4i < 8; m4i++) {
        int m4 = (m4i + 2 * cl) & 7;
#pragma unroll
        for (int e = 0; e < 4; e++)
            w2c[m4i * 4 + e] = sW2[(cl * RHH + m4 * 4 + e) * NHH + chh];
    }
    float b2c = sB2[c];
    int jb = (t >> 5) * 8;
    float* dstrow = g_refw + ((((size_t)cl * BB + b) * NHH + chh) * LL + i) * LL;

    for (int j0 = 0; j0 < LL; j0 += 64) {
        for (int idx = t; idx < 64 * RIN; idx += 256) {
            int jl = idx / RIN, k = idx % RIN;
            sRC[k * 68 + jl] = rcbase[(size_t)(j0 + jl) * RIN + k];
        }
        __syncthreads();

        float acc[8][4];
#pragma unroll
        for (int a = 0; a < 8; a++)
#pragma unroll
            for (int q = 0; q < 4; q++) acc[a][q] = 0.0f;

#pragma unroll 4
        for (int k = 0; k < RIN; k++) {
            float4 bv = *(const float4*)&sW1[k * 128 + tx * 4];
            float4 a0 = *(const float4*)&sRC[k * 68 + ty * 8];
            float4 a1 = *(const float4*)&sRC[k * 68 + ty * 8 + 4];
            float aj[8] = {a0.x, a0.y, a0.z, a0.w, a1.x, a1.y, a1.z, a1.w};
#pragma unroll
            for (int a = 0; a < 8; a++) {
                acc[a][0] += aj[a] * bv.x;
                acc[a][1] += aj[a] * bv.y;
                acc[a][2] += aj[a] * bv.z;
                acc[a][3] += aj[a] * bv.w;
            }
        }
        float4 bias = *(const float4*)&sB1[tx * 4];
#pragma unroll
        for (int a = 0; a < 8; a++) {
            float4 h4;
            h4.x = fmaxf(acc[a][0] + bias.x, 0.0f);
            h4.y = fmaxf(acc[a][1] + bias.y, 0.0f);
            h4.z = fmaxf(acc[a][2] + bias.z, 0.0f);
            h4.w = fmaxf(acc[a][3] + bias.w, 0.0f);
            *(float4*)&sHid[(ty * 8 + a) * 132 + tx * 4] = h4;
        }
        __syncthreads();

        // stage B: rotated m4 order -> the four cl groups hit disjoint banks
        float buf[8];
#pragma unroll
        for (int a = 0; a < 8; a++) {
            int jl = jb + a;
            const float* hrow = &sHid[jl * 132 + cl * RHH];
            float o = b2c;
#pragma unroll
            for (int m4i = 0; m4i < 8; m4i++) {
                int m4 = (m4i + 2 * cl) & 7;
                float4 h4 = *(const float4*)&hrow[m4 * 4];
                o += h4.x * w2c[m4i * 4] + h4.y * w2c[m4i * 4 + 1]
                   + h4.z * w2c[m4i * 4 + 2] + h4.w * w2c[m4i * 4 + 3];
            }
            int j = j0 + jl;
            buf[a] = (sMask[j] != 0.0f) ? o : -1e30f;
        }
        *(float4*)&dstrow[j0 + jb]     = *(float4*)&buf[0];
        *(float4*)&dstrow[j0 + jb + 4] = *(float4*)&buf[4];
        __syncthreads();
    }
}

// ---------- 3xTF32 mma GEMM: C[3072,512] = A @ W + bias ----------
template <int MODE>
__global__ void __launch_bounds__(256) k_mm(
        const float* __restrict__ W0, const float* __restrict__ W1,
        const float* __restrict__ W2, const float* __restrict__ b0,
        const float* __restrict__ b1, const float* __restrict__ b2) {
    __shared__ float Ah[64 * 20], Al[64 * 20], Bh[16 * 72], Bl[16 * 72];
    int sel = (MODE == 1) ? (blockIdx.y >> 3) : 0;
    const float* A    = (MODE == 0) ? g_ao : g_h;
    const float* W    = (sel == 0) ? W0 : (sel == 1) ? W1 : W2;
    const float* bias = (sel == 0) ? b0 : (sel == 1) ? b1 : b2;
    int m0 = blockIdx.x * 64;
    int n0 = ((MODE == 1) ? (blockIdx.y & 7) : blockIdx.y) * 64;
    int t = threadIdx.x, lane = t & 31, wid = t >> 5;
    int g = lane >> 2, tg = lane & 3;
    int wm = wid & 1, wn = wid >> 1;
    int ar = t >> 2, ac = t & 3;
    int wr = t >> 4, wc = t & 15;

    float acc[2][2][4] = {};

    for (int k0 = 0; k0 < CC; k0 += 16) {
        float4 a4 = *(const float4*)&A[(size_t)(m0 + ar) * CC + k0 + ac * 4];
        float4 h4, l4;
        split4(a4, h4, l4);
        *(float4*)&Ah[ar * 20 + ac * 4] = h4;
        *(float4*)&Al[ar * 20 + ac * 4] = l4;
        float4 w4 = *(const float4*)&W[(size_t)(k0 + wr) * CC + n0 + wc * 4];
        split4(w4, h4, l4);
        *(float4*)&Bh[wr * 72 + wc * 4] = h4;
        *(float4*)&Bl[wr * 72 + wc * 4] = l4;
        __syncthreads();

#pragma unroll
        for (int kk = 0; kk < 16; kk += 8) {
            uint32_t ah[2][4], al[2][4];
#pragma unroll
            for (int mt = 0; mt < 2; mt++) {
                int mb = wm * 32 + mt * 16;
                ah[mt][0] = __float_as_uint(Ah[(mb + g) * 20 + kk + tg]);
                ah[mt][1] = __float_as_uint(Ah[(mb + g + 8) * 20 + kk + tg]);
                ah[mt][2] = __float_as_uint(Ah[(mb + g) * 20 + kk + tg + 4]);
                ah[mt][3] = __float_as_uint(Ah[(mb + g + 8) * 20 + kk + tg + 4]);
                al[mt][0] = __float_as_uint(Al[(mb + g) * 20 + kk + tg]);
                al[mt][1] = __float_as_uint(Al[(mb + g + 8) * 20 + kk + tg]);
                al[mt][2] = __float_as_uint(Al[(mb + g) * 20 + kk + tg + 4]);
                al[mt][3] = __float_as_uint(Al[(mb + g + 8) * 20 + kk + tg + 4]);
            }
#pragma unroll
            for (int nt = 0; nt < 2; nt++) {
                int nb = wn * 16 + nt * 8;
                uint32_t bh0 = __float_as_uint(Bh[(kk + tg) * 72 + nb + g]);
                uint32_t bh1 = __float_as_uint(Bh[(kk + tg + 4) * 72 + nb + g]);
                uint32_t bl0 = __float_as_uint(Bl[(kk + tg) * 72 + nb + g]);
                uint32_t bl1 = __float_as_uint(Bl[(kk + tg + 4) * 72 + nb + g]);
#pragma unroll
                for (int mt = 0; mt < 2; mt++) {
                    mma_tf32(acc[mt][nt], ah[mt], bh0, bh1);
                    mma_tf32(acc[mt][nt], al[mt], bh0, bh1);
                    mma_tf32(acc[mt][nt], ah[mt], bl0, bl1);
                }
            }
        }
        __syncthreads();
    }

#pragma unroll
    for (int mt = 0; mt < 2; mt++) {
#pragma unroll
        for (int nt = 0; nt < 2; nt++) {
#pragma unroll
            for (int rh = 0; rh < 2; rh++) {
                int m = m0 + wm * 32 + mt * 16 + g + rh * 8;
                int n = n0 + wn * 16 + nt * 8 + 2 * tg;
                float v0 = acc[mt][nt][rh * 2]     + bias[n];
                float v1 = acc[mt][nt][rh * 2 + 1] + bias[n + 1];
                if (MODE == 0) {
                    *(float2*)&g_t1[(size_t)m * CC + n] = make_float2(v0, v1);
                } else {
                    int bi = m / LL, ii = m % LL, nh = n >> 6, d = n & 63;
                    float* OUT = (sel == 0) ? g_q : (sel == 1) ? g_k : g_v;
                    *(float2*)&OUT[((size_t)(bi * NHH + nh) * LL + ii) * DKK + d] =
                        make_float2(v0, v1);
                }
            }
        }
    }
}

// ---------- scores = QK^T/8 via 3xTF32 mma; 64x64 tile, K=64 ----------
__global__ void __launch_bounds__(256) k_scores_mma() {
    __shared__ float Ah[64 * 20], Al[64 * 20], Bh[64 * 20], Bl[64 * 20];
    int z = blockIdx.z, b = z >> 3;
    int i0 = blockIdx.x * 64, j0 = blockIdx.y * 64;
    const float* Q = g_q + (size_t)z * LL * DKK;
    const float* K = g_k + (size_t)z * LL * DKK;
    int t = threadIdx.x, lane = t & 31, wid = t >> 5;
    int g = lane >> 2, tg = lane & 3;
    int wm = wid & 1, wn = wid >> 1;
    int ar = t >> 2, ac = t & 3;
    float acc[2][2][4] = {};

    for (int k0 = 0; k0 < DKK; k0 += 16) {
        float4 a4 = *(const float4*)&Q[(size_t)(i0 + ar) * DKK + k0 + ac * 4];
        float4 h4, l4;
        split4(a4, h4, l4);
        *(float4*)&Ah[ar * 20 + ac * 4] = h4;
        *(float4*)&Al[ar * 20 + ac * 4] = l4;
        float4 u4 = *(const float4*)&K[(size_t)(j0 + ar) * DKK + k0 + ac * 4];
        split4(u4, h4, l4);
        *(float4*)&Bh[ar * 20 + ac * 4] = h4;   // layout [j][k]
        *(float4*)&Bl[ar * 20 + ac * 4] = l4;
        __syncthreads();

#pragma unroll
        for (int kk = 0; kk < 16; kk += 8) {
            uint32_t ah[2][4], al[2][4];
#pragma unroll
            for (int mt = 0; mt < 2; mt++) {
                int mb = wm * 32 + mt * 16;
                ah[mt][0] = __float_as_uint(Ah[(mb + g) * 20 + kk + tg]);
                ah[mt][1] = __float_as_uint(Ah[(mb + g + 8) * 20 + kk + tg]);
                ah[mt][2] = __float_as_uint(Ah[(mb + g) * 20 + kk + tg + 4]);
                ah[mt][3] = __float_as_uint(Ah[(mb + g + 8) * 20 + kk + tg + 4]);
                al[mt][0] = __float_as_uint(Al[(mb + g) * 20 + kk + tg]);
                al[mt][1] = __float_as_uint(Al[(mb + g + 8) * 20 + kk + tg]);
                al[mt][2] = __float_as_uint(Al[(mb + g) * 20 + kk + tg + 4]);
                al[mt][3] = __float_as_uint(Al[(mb + g + 8) * 20 + kk + tg + 4]);
            }
#pragma unroll
            for (int nt = 0; nt < 2; nt++) {
                int nb = wn * 16 + nt * 8;
                uint32_t bh0 = __float_as_uint(Bh[(nb + g) * 20 + kk + tg]);
                uint32_t bh1 = __float_as_uint(Bh[(nb + g) * 20 + kk + tg + 4]);
                uint32_t bl0 = __float_as_uint(Bl[(nb + g) * 20 + kk + tg]);
                uint32_t bl1 = __float_as_uint(Bl[(nb + g) * 20 + kk + tg + 4]);
#pragma unroll
                for (int mt = 0; mt < 2; mt++) {
                    mma_tf32(acc[mt][nt], ah[mt], bh0, bh1);
                    mma_tf32(acc[mt][nt], al[mt], bh0, bh1);
                    mma_tf32(acc[mt][nt], ah[mt], bl0, bl1);
                }
            }
        }
        __syncthreads();
    }

    float* out = g_sc + (size_t)z * LL * LL;
#pragma unroll
    for (int mt = 0; mt < 2; mt++) {
#pragma unroll
        for (int rh = 0; rh < 2; rh++) {
            int i = i0 + wm * 32 + mt * 16 + g + rh * 8;
            float mi = g_mask[b * LL + i];
#pragma unroll
            for (int nt = 0; nt < 2; nt++) {
                int j = j0 + wn * 16 + nt * 8 + 2 * tg;
                float mj0 = g_mask[b * LL + j];
                float mj1 = g_mask[b * LL + j + 1];
                float v0 = (mi != 0.0f && mj0 != 0.0f) ? acc[mt][nt][rh * 2] * 0.125f : -1e30f;
                float v1 = (mi != 0.0f && mj1 != 0.0f) ? acc[mt][nt][rh * 2 + 1] * 0.125f : -1e30f;
                *(float2*)&out[(size_t)i * LL + j] = make_float2(v0, v1);
            }
        }
    }
}

// ---------- dual softmax + combine ----------
__global__ void k_softcomb(int l) {
    int gw = blockIdx.x * 4 + (threadIdx.x >> 5);
    int lane = threadIdx.x & 31;
    int row_i = gw % LL;
    int z = gw / LL;
    int b = z >> 3;
    float* sc = g_sc + (size_t)z * LL * LL + (size_t)row_i * LL;
    if (g_mask[b * LL + row_i] == 0.0f) {
        for (int j = lane; j < LL; j += 32) sc[j] = 0.0f;
        return;
    }
    const float* rw = g_refw + (((size_t)l * BB * NHH + z) * LL + row_i) * LL;
    float vals[12], rv[12];
    float mx = -3.4e38f, rmx = -3.4e38f;
#pragma unroll
    for (int r = 0; r < 12; r++) {
        vals[r] = sc[lane + r * 32]; mx = fmaxf(mx, vals[r]);
        rv[r] = rw[lane + r * 32];   rmx = fmaxf(rmx, rv[r]);
    }
#pragma unroll
    for (int o = 16; o > 0; o >>= 1) {
        mx  = fmaxf(mx,  __shfl_xor_sync(0xffffffffu, mx, o));
        rmx = fmaxf(rmx, __shfl_xor_sync(0xffffffffu, rmx, o));
    }
    float s = 0.0f, rs = 0.0f;
#pragma unroll
    for (int r = 0; r < 12; r++) {
        vals[r] = __expf(vals[r] - mx); s += vals[r];
        rv[r]   = __expf(rv[r] - rmx);  rs += rv[r];
    }
#pragma unroll
    for (int o = 16; o > 0; o >>= 1) {
        s  += __shfl_xor_sync(0xffffffffu, s, o);
        rs += __shfl_xor_sync(0xffffffffu, rs, o);
    }
    float inv = 0.5f / s, rinv = 0.5f / rs;
#pragma unroll
    for (int r = 0; r < 12; r++)
        sc[lane + r * 32] = vals[r] * inv + rv[r] * rinv;
}

// ---------- out = comb @ V via 3xTF32 mma; 64x64 tile, K=384 ----------
__global__ void __launch_bounds__(256) k_av_mma() {
    __shared__ float Ah[64 * 20], Al[64 * 20], Bh[16 * 72], Bl[16 * 72];
    int z = blockIdx.y, b = z >> 3, nh = z & 7;
    const float* Am = g_sc + (size_t)z * LL * LL;
    const float* V  = g_v + (size_t)z * LL * DKK;
    int m0 = blockIdx.x * 64;
    int t = threadIdx.x, lane = t & 31, wid = t >> 5;
    int g = lane >> 2, tg = lane & 3;
    int wm = wid & 1, wn = wid >> 1;
    int ar = t >> 2, ac = t & 3;
    int wr = t >> 4, wc = t & 15;
    float acc[2][2][4] = {};

    for (int k0 = 0; k0 < LL; k0 += 16) {
        float4 a4 = *(const float4*)&Am[(size_t)(m0 + ar) * LL + k0 + ac * 4];
        float4 h4, l4;
        split4(a4, h4, l4);
        *(float4*)&Ah[ar * 20 + ac * 4] = h4;
        *(float4*)&Al[ar * 20 + ac * 4] = l4;
        float4 v4 = *(const float4*)&V[(size_t)(k0 + wr) * DKK + wc * 4];
        split4(v4, h4, l4);
        *(float4*)&Bh[wr * 72 + wc * 4] = h4;    // layout [k][n]
        *(float4*)&Bl[wr * 72 + wc * 4] = l4;
        __syncthreads();

#pragma unroll
        for (int kk = 0; kk < 16; kk += 8) {
            uint32_t ah[2][4], al[2][4];
#pragma unroll
            for (int mt = 0; mt < 2; mt++) {
                int mb = wm * 32 + mt * 16;
                ah[mt][0] = __float_as_uint(Ah[(mb + g) * 20 + kk + tg]);
                ah[mt][1] = __float_as_uint(Ah[(mb + g + 8) * 20 + kk + tg]);
                ah[mt][2] = __float_as_uint(Ah[(mb + g) * 20 + kk + tg + 4]);
                ah[mt][3] = __float_as_uint(Ah[(mb + g + 8) * 20 + kk + tg + 4]);
                al[mt][0] = __float_as_uint(Al[(mb + g) * 20 + kk + tg]);
                al[mt][1] = __float_as_uint(Al[(mb + g + 8) * 20 + kk + tg]);
                al[mt][2] = __float_as_uint(Al[(mb + g) * 20 + kk + tg + 4]);
                al[mt][3] = __float_as_uint(Al[(mb + g + 8) * 20 + kk + tg + 4]);
            }
#pragma unroll
            for (int nt = 0; nt < 2; nt++) {
                int nb = wn * 16 + nt * 8;
                uint32_t bh0 = __float_as_uint(Bh[(kk + tg) * 72 + nb + g]);
                uint32_t bh1 = __float_as_uint(Bh[(kk + tg + 4) * 72 + nb + g]);
                uint32_t bl0 = __float_as_uint(Bl[(kk + tg) * 72 + nb + g]);
                uint32_t bl1 = __float_as_uint(Bl[(kk + tg + 4) * 72 + nb + g]);
#pragma unroll
                for (int mt = 0; mt < 2; mt++) {
                    mma_tf32(acc[mt][nt], ah[mt], bh0, bh1);
                    mma_tf32(acc[mt][nt], al[mt], bh0, bh1);
                    mma_tf32(acc[mt][nt], ah[mt], bl0, bl1);
                }
            }
        }
        __syncthreads();
    }

#pragma unroll
    for (int mt = 0; mt < 2; mt++) {
#pragma unroll
        for (int nt = 0; nt < 2; nt++) {
#pragma unroll
            for (int rh = 0; rh < 2; rh++) {
                int i = m0 + wm * 32 + mt * 16 + g + rh * 8;
                int d = wn * 16 + nt * 8 + 2 * tg;
                *(float2*)&g_ao[((size_t)(b * LL + i)) * CC + nh * DKK + d] =
                    make_float2(acc[mt][nt][rh * 2], acc[mt][nt][rh * 2 + 1]);
            }
        }
    }
}

// ---------- residual + layernorm ----------
template <int FINAL>
__global__ void k_ln(const float* __restrict__ gam, const float* __restrict__ bet) {
    __shared__ float red[8];
    int r = blockIdx.x, t = threadIdx.x;
    const float* a = g_h + (size_t)r * CC;
    const float* bb = g_t1 + (size_t)r * CC;
    float v[4];
    float s = 0.0f;
#pragma unroll
    for (int q = 0; q < 4; q++) {
        int cidx = t + q * 128;
        float x = FINAL ? a[cidx] : (a[cidx] + bb[cidx]);
        v[q] = x;
        s += x;
    }
#pragma unroll
    for (int o = 16; o > 0; o >>= 1) s += __shfl_xor_sync(0xffffffffu, s, o);
    if ((t & 31) == 0) red[t >> 5] = s;
    __syncthreads();
    float mu = (red[0] + red[1] + red[2] + red[3]) * (1.0f / 512.0f);
    float vs = 0.0f;
#pragma unroll
    for (int q = 0; q < 4; q++) { float d = v[q] - mu; vs += d * d; }
#pragma unroll
    for (int o = 16; o > 0; o >>= 1) vs += __shfl_xor_sync(0xffffffffu, vs, o);
    if ((t & 31) == 0) red[4 + (t >> 5)] = vs;
    __syncthreads();
    float var = (red[4] + red[5] + red[6] + red[7]) * (1.0f / 512.0f);
    float rsr = rsqrtf(var + 1e-5f);
    float* out = FINAL ? (g_t1 + (size_t)r * CC) : (g_h + (size_t)r * CC);
#pragma unroll
    for (int q = 0; q < 4; q++) {
        int cidx = t + q * 128;
        out[cidx] = (v[q] - mu) * rsr * gam[cidx] + bet[cidx];
    }
}

// ---------- final masked sum ----------
__global__ void k_finred(float* __restrict__ out) {
    int b = blockIdx.x;
    int cidx = blockIdx.y * 128 + threadIdx.x;
    float s = 0.0f;
#pragma unroll 4
    for (int i = 0; i < LL; i++)
        s += g_mask[b * LL + i] * g_t1[((size_t)(b * LL + i)) * CC + cidx];
    out[b * CC + cidx] = s;
}

// ---------- host launch ----------
extern "C" void kernel_launch(void* const* d_in, const int* in_sizes, int n_in,
                              void* d_out, int out_size) {
    const float* x            = (const float*)d_in[0];
    const unsigned char* mraw = (const unsigned char*)d_in[1];
    const float* refCov       = (const float*)d_in[2];
    const float* Wq  = (const float*)d_in[3];
    const float* bq  = (const float*)d_in[4];
    const float* Wk  = (const float*)d_in[5];
    const float* bk  = (const float*)d_in[6];
    const float* Wv  = (const float*)d_in[7];
    const float* bv  = (const float*)d_in[8];
    const float* Wo  = (const float*)d_in[9];
    const float* bo  = (const float*)d_in[10];
    const float* Wr1 = (const float*)d_in[11];
    const float* br1 = (const float*)d_in[12];
    const float* Wr2 = (const float*)d_in[13];
    const float* br2 = (const float*)d_in[14];
    const float* ln_g = (const float*)d_in[15];
    const float* ln_b = (const float*)d_in[16];
    const float* fn_g = (const float*)d_in[17];
    const float* fn_b = (const float*)d_in[18];
    (void)in_sizes; (void)n_in; (void)out_size;

    cudaFuncSetAttribute(k_ref, cudaFuncAttributeMaxDynamicSharedMemorySize,
                         REF_SMEM_FLOATS * (int)sizeof(float));

    k_detect<<<1, 256>>>(mraw);
    k_mask<<<(BB * LL + 255) / 256, 256>>>(mraw);
    k_hinit<<<(BB * LL * CC) / 256, 256>>>(x);
    k_ref<<<BB * LL, 256, REF_SMEM_FLOATS * sizeof(float)>>>(refCov, Wr1, br1, Wr2, br2);

    for (int l = 0; l < NLL; l++) {
        const float* wq = Wq + (size_t)l * CC * CC;
        const float* wk = Wk + (size_t)l * CC * CC;
        const float* wv = Wv + (size_t)l * CC * CC;
        const float* wo = Wo + (size_t)l * CC * CC;
        k_mm<1><<<dim3(48, 24), 256>>>(wq, wk, wv, bq + l * CC, bk + l * CC, bv + l * CC);
        k_scores_mma<<<dim3(6, 6, BB * NHH), 256>>>();
        k_softcomb<<<(BB * NHH * LL) / 4, 128>>>(l);
        k_av_mma<<<dim3(6, BB * NHH), 256>>>();
        k_mm<0><<<dim3(48, 8), 256>>>(wo, bo + l * CC, nullptr, bo + l * CC, nullptr, nullptr);
        k_ln<0><<<BB * LL, 128>>>(ln_g + l * CC, ln_b + l * CC);
    }
    k_ln<1><<<BB * LL, 128>>>(fn_g, fn_b);
    k_finred<<<dim3(BB, CC / 128), 128>>>((float*)d_out);
}